// round 4
// baseline (speedup 1.0000x reference)
#include <cuda_runtime.h>
#include <cstdint>

#define B_  8
#define C_  128
#define H_  192
#define W_  448
#define ND  49

#define TX  32
#define TY  16
#define KC  8
#define NCHUNK (C_ / KC)
#define NT  384

#define S2_ROW 44                   // logical x in [-4, TX+7] -> idx = x+4
#define S2_CH  ((TY + 6) * S2_ROW)  // 22*44 = 968
#define S2_SIZE (KC * S2_CH)        // 7744 floats per buffer
#define SMEM_BYTES (2 * S2_SIZE * sizeof(float))  // 61952 B

__device__ __forceinline__ uint32_t sptr(const void* p) {
    return (uint32_t)__cvta_generic_to_shared(p);
}
__device__ __forceinline__ void cp16(void* dst, const float* src, bool pred) {
    int bytes = pred ? 16 : 0;
    asm volatile("cp.async.cg.shared.global [%0], [%1], 16, %2;\n"
                 :: "r"(sptr(dst)), "l"(src), "r"(bytes));
}
__device__ __forceinline__ void cp4(void* dst, const float* src, bool pred) {
    int bytes = pred ? 4 : 0;
    asm volatile("cp.async.ca.shared.global [%0], [%1], 4, %2;\n"
                 :: "r"(sptr(dst)), "l"(src), "r"(bytes));
}
__device__ __forceinline__ void cp_commit() {
    asm volatile("cp.async.commit_group;\n" ::: "memory");
}

__device__ __forceinline__ void load_chunk(
    float* __restrict__ s2,
    const float* __restrict__ sbase,
    int c0, int x0, int y0, int tid)
{
    const size_t HW = (size_t)H_ * W_;
    // ---- interior: 8ch x 22 rows x 8 float4 = 1408 units ----
#pragma unroll
    for (int it = 0; it < 4; ++it) {
        int u = tid + it * NT;
        if (it < 3 || u < 1408) {
            int c = u / 176;
            int rem = u - c * 176;
            int row = rem >> 3;
            int q = rem & 7;
            int gy = y0 - 3 + row;
            bool p = (gy >= 0) && (gy < H_);
            int gyc = gy < 0 ? 0 : (gy >= H_ ? H_ - 1 : gy);
            const float* src = sbase + (size_t)(c0 + c) * HW + (size_t)gyc * W_ + x0 + q * 4;
            cp16(s2 + c * S2_CH + row * S2_ROW + 4 + q * 4, src, p);
        }
    }
    // ---- edges: 8ch x 22 rows x 6 scalars = 1056 units ----
#pragma unroll
    for (int it = 0; it < 3; ++it) {
        int u = tid + it * NT;
        if (it < 2 || u < 1056) {
            int c = u / 132;
            int rem = u - c * 132;
            int row = rem / 6;
            int e = rem - row * 6;
            int x = (e < 3) ? (e - 3) : (TX + e - 3);
            int gy = y0 - 3 + row;
            int gx = x0 + x;
            bool p = (gy >= 0) && (gy < H_) && (gx >= 0) && (gx < W_);
            int gyc = gy < 0 ? 0 : (gy >= H_ ? H_ - 1 : gy);
            int gxc = gx < 0 ? 0 : (gx >= W_ ? W_ - 1 : gx);
            const float* src = sbase + (size_t)(c0 + c) * HW + (size_t)gyc * W_ + gxc;
            cp4(s2 + c * S2_CH + row * S2_ROW + (x + 4), src, p);
        }
    }
}

// One smem row segment: displacements di in [DI0, DI1), minimal aligned loads.
// vrow points at smem index txl*4 of the row; v[j] = logical x offset (j-4).
// acc is packed: (di - DI0)*4 + p.
template<int DI0, int DI1>
__device__ __forceinline__ void row_acc(
    const float* __restrict__ vrow, float4 f, float* __restrict__ acc)
{
    constexpr int JLO = DI0 + 1;
    constexpr int JHI = DI1 + 3 - 1 + 1;   // max j = (DI1-1)+3+1
    constexpr int B0 = JLO / 4;
    constexpr int B1 = JHI / 4;
    float v[16];
#pragma unroll
    for (int bq = B0; bq <= B1; ++bq) {
        float4 t = ((const float4*)vrow)[bq];
        v[bq * 4 + 0] = t.x; v[bq * 4 + 1] = t.y;
        v[bq * 4 + 2] = t.z; v[bq * 4 + 3] = t.w;
    }
#pragma unroll
    for (int di = DI0; di < DI1; ++di) {
        acc[(di - DI0) * 4 + 0] += f.x * v[di + 1];
        acc[(di - DI0) * 4 + 1] += f.y * v[di + 2];
        acc[(di - DI0) * 4 + 2] += f.z * v[di + 3];
        acc[(di - DI0) * 4 + 3] += f.w * v[di + 4];
    }
}

// Segment tables per group: (rr, di0, di1, acc offset in floats)
// G0: d[0,17)  = rr0[0,7) rr1[0,7) rr2[0,3)   -> 68 floats
// G1: d[17,34) = rr2[3,7) rr3[0,7) rr4[0,6)   -> 68 floats
// G2: d[34,49) = rr4[6,7) rr5[0,7) rr6[0,7)   -> 60 floats
template<int G>
__device__ __forceinline__ void accumulate(
    const float* __restrict__ s2,
    const float* __restrict__ fpix, int c0,
    int tyl, int txl, float* __restrict__ acc)
{
    const size_t HW = (size_t)H_ * W_;
    float4 f0 = *(const float4*)(fpix + (size_t)(c0 + 0) * HW);
    float4 f1 = *(const float4*)(fpix + (size_t)(c0 + 1) * HW);

#pragma unroll 1
    for (int c = 0; c < KC; ++c) {
        float4 f = f0;
        f0 = f1;
        int cn = c0 + c + 2;
        if (cn > C_ - 1) cn = C_ - 1;
        f1 = *(const float4*)(fpix + (size_t)cn * HW);

        const float* rb = s2 + c * S2_CH + tyl * S2_ROW + txl * 4;
        if (G == 0) {
            row_acc<0, 7>(rb + 0 * S2_ROW, f, acc + 0);
            row_acc<0, 7>(rb + 1 * S2_ROW, f, acc + 28);
            row_acc<0, 3>(rb + 2 * S2_ROW, f, acc + 56);
        } else if (G == 1) {
            row_acc<3, 7>(rb + 2 * S2_ROW, f, acc + 0);
            row_acc<0, 7>(rb + 3 * S2_ROW, f, acc + 16);
            row_acc<0, 6>(rb + 4 * S2_ROW, f, acc + 44);
        } else {
            row_acc<6, 7>(rb + 4 * S2_ROW, f, acc + 0);
            row_acc<0, 7>(rb + 5 * S2_ROW, f, acc + 4);
            row_acc<0, 7>(rb + 6 * S2_ROW, f, acc + 32);
        }
    }
}

__device__ __forceinline__ void store_seg(
    float* __restrict__ out, const float* __restrict__ acc,
    int b, int y, int x, int dbase, int nd)
{
    const float invC = 1.0f / (float)C_;
#pragma unroll
    for (int i = 0; i < nd; ++i) {
        float4 o;
        o.x = acc[i * 4 + 0] * invC;
        o.y = acc[i * 4 + 1] * invC;
        o.z = acc[i * 4 + 2] * invC;
        o.w = acc[i * 4 + 3] * invC;
        *(float4*)(out + (((size_t)b * ND + dbase + i) * H_ + y) * W_ + x) = o;
    }
}

__global__ void __launch_bounds__(NT, 1)
corr_kernel(const float* __restrict__ first,
            const float* __restrict__ second,
            float* __restrict__ out)
{
    extern __shared__ float smem[];
    const int tid = threadIdx.x;
    const int wg   = tid >> 7;        // warpgroup 0,1,2 (displacement split)
    const int wtid = tid & 127;
    const int bx = blockIdx.x, by = blockIdx.y, b = blockIdx.z;
    const int x0 = bx * TX, y0 = by * TY;
    const int txl = wtid & 7;         // 0..7, owns 4 x-pixels
    const int tyl = wtid >> 3;        // 0..15, one y-row

    const size_t HW = (size_t)H_ * W_;
    const float* fbase = first  + (size_t)b * C_ * HW;
    const float* sbase = second + (size_t)b * C_ * HW;
    const float* fpix  = fbase + (size_t)(y0 + tyl) * W_ + x0 + txl * 4;

    float acc[68];
#pragma unroll
    for (int i = 0; i < 68; ++i) acc[i] = 0.0f;

    load_chunk(smem, sbase, 0, x0, y0, tid);
    cp_commit();

#pragma unroll 1
    for (int k = 0; k < NCHUNK; ++k) {
        if (k < NCHUNK - 1) {
            float* nb = smem + ((k + 1) & 1) * S2_SIZE;
            load_chunk(nb, sbase, (k + 1) * KC, x0, y0, tid);
            cp_commit();
            asm volatile("cp.async.wait_group 1;\n" ::: "memory");
        } else {
            asm volatile("cp.async.wait_group 0;\n" ::: "memory");
        }
        __syncthreads();

        const float* s2 = smem + (k & 1) * S2_SIZE;

        if (wg == 0)      accumulate<0>(s2, fpix, k * KC, tyl, txl, acc);
        else if (wg == 1) accumulate<1>(s2, fpix, k * KC, tyl, txl, acc);
        else              accumulate<2>(s2, fpix, k * KC, tyl, txl, acc);

        __syncthreads();
    }

    const int y = y0 + tyl;
    const int x = x0 + txl * 4;
    if (wg == 0) {
        store_seg(out, acc, b, y, x, 0, 17);
    } else if (wg == 1) {
        store_seg(out, acc, b, y, x, 17, 17);
    } else {
        store_seg(out, acc, b, y, x, 34, 15);
    }
}

extern "C" void kernel_launch(void* const* d_in, const int* in_sizes, int n_in,
                              void* d_out, int out_size)
{
    const float* first  = (const float*)d_in[0];
    const float* second = (const float*)d_in[1];
    float* out = (float*)d_out;

    cudaFuncSetAttribute(corr_kernel,
                         cudaFuncAttributeMaxDynamicSharedMemorySize,
                         (int)SMEM_BYTES);

    dim3 grid(W_ / TX, H_ / TY, B_);   // 14 x 12 x 8 = 1344 CTAs
    dim3 block(NT);
    corr_kernel<<<grid, block, SMEM_BYTES>>>(first, second, out);
}

// round 5
// speedup vs baseline: 1.5737x; 1.5737x over previous
#include <cuda_runtime.h>
#include <cstdint>

#define B_  8
#define C_  128
#define H_  192
#define W_  448
#define ND  49

#define TX  32
#define TY  16
#define KC  8
#define NCHUNK (C_ / KC)
#define NT  192

#define S1_ROW 36                   // padded to avoid f-load bank conflicts
#define S1_CH  (TY * S1_ROW)        // 576
#define S2_ROW 44                   // logical x in [-4, TX+7] -> idx = x+4
#define S2_CH  ((TY + 6) * S2_ROW)  // 968
#define S1_SIZE (KC * S1_CH)        // 4608
#define S2_SIZE (KC * S2_CH)        // 7744
#define BUF_SIZE (S1_SIZE + S2_SIZE)               // 12352 floats
#define SMEM_BYTES (2 * BUF_SIZE * sizeof(float))  // 98816 B

__device__ __forceinline__ uint32_t sptr(const void* p) {
    return (uint32_t)__cvta_generic_to_shared(p);
}
__device__ __forceinline__ void cp16(void* dst, const float* src, bool pred) {
    int bytes = pred ? 16 : 0;
    asm volatile("cp.async.cg.shared.global [%0], [%1], 16, %2;\n"
                 :: "r"(sptr(dst)), "l"(src), "r"(bytes));
}
__device__ __forceinline__ void cp4(void* dst, const float* src, bool pred) {
    int bytes = pred ? 4 : 0;
    asm volatile("cp.async.ca.shared.global [%0], [%1], 4, %2;\n"
                 :: "r"(sptr(dst)), "l"(src), "r"(bytes));
}
__device__ __forceinline__ void cp_commit() {
    asm volatile("cp.async.commit_group;\n" ::: "memory");
}

__device__ __forceinline__ void load_chunk(
    float* __restrict__ s1, float* __restrict__ s2,
    const float* __restrict__ fbase, const float* __restrict__ sbase,
    int c0, int x0, int y0, int tid)
{
    const size_t HW = (size_t)H_ * W_;
    // ---- first tile: 8ch x 16 rows x 8 float4 = 1024 units ----
#pragma unroll
    for (int it = 0; it < 6; ++it) {
        int u = tid + it * NT;
        if (it < 5 || u < 1024) {
            int c = u >> 7;
            int rem = u & 127;
            int row = rem >> 3;
            int q = rem & 7;
            const float* src = fbase + (size_t)(c0 + c) * HW + (size_t)(y0 + row) * W_ + x0 + q * 4;
            cp16(s1 + c * S1_CH + row * S1_ROW + q * 4, src, true);
        }
    }
    // ---- second interior: 8ch x 22 rows x 8 float4 = 1408 units ----
#pragma unroll
    for (int it = 0; it < 8; ++it) {
        int u = tid + it * NT;
        if (it < 7 || u < 1408) {
            int c = u / 176;
            int rem = u - c * 176;
            int row = rem >> 3;
            int q = rem & 7;
            int gy = y0 - 3 + row;
            bool p = (gy >= 0) && (gy < H_);
            int gyc = gy < 0 ? 0 : (gy >= H_ ? H_ - 1 : gy);
            const float* src = sbase + (size_t)(c0 + c) * HW + (size_t)gyc * W_ + x0 + q * 4;
            cp16(s2 + c * S2_CH + row * S2_ROW + 4 + q * 4, src, p);
        }
    }
    // ---- second edges: 8ch x 22 rows x 6 scalars = 1056 units ----
#pragma unroll
    for (int it = 0; it < 6; ++it) {
        int u = tid + it * NT;
        if (it < 5 || u < 1056) {
            int c = u / 132;
            int rem = u - c * 132;
            int row = rem / 6;
            int e = rem - row * 6;
            int x = (e < 3) ? (e - 3) : (TX + e - 3);
            int gy = y0 - 3 + row;
            int gx = x0 + x;
            bool p = (gy >= 0) && (gy < H_) && (gx >= 0) && (gx < W_);
            int gyc = gy < 0 ? 0 : (gy >= H_ ? H_ - 1 : gy);
            int gxc = gx < 0 ? 0 : (gx >= W_ ? W_ - 1 : gx);
            const float* src = sbase + (size_t)(c0 + c) * HW + (size_t)gyc * W_ + gxc;
            cp4(s2 + c * S2_CH + row * S2_ROW + (x + 4), src, p);
        }
    }
}

// One smem row, displacements di in [DI0, DI1), 8 x-pixels per thread.
// vrow = row base at float index txl*8 (padded coords). j = di + p + 1.
// acc packed as (di - DI0)*8 + p.
template<int DI0, int DI1>
__device__ __forceinline__ void row_acc(
    const float* __restrict__ vrow, const float (&f)[8], float* __restrict__ acc)
{
    constexpr int B0 = (DI0 + 1) / 4;
    constexpr int B1 = (DI1 + 7) / 4;   // max j = (DI1-1) + 7 + 1
    float v[16];
#pragma unroll
    for (int bq = B0; bq <= B1; ++bq) {
        float4 t = ((const float4*)vrow)[bq];
        v[bq * 4 + 0] = t.x; v[bq * 4 + 1] = t.y;
        v[bq * 4 + 2] = t.z; v[bq * 4 + 3] = t.w;
    }
#pragma unroll
    for (int di = DI0; di < DI1; ++di) {
#pragma unroll
        for (int p = 0; p < 8; ++p) {
            acc[(di - DI0) * 8 + p] += f[p] * v[di + p + 1];
        }
    }
}

// Group segments (contiguous in flattened d):
// G0: d[ 0,16) = rr0[0,7) rr1[0,7) rr2[0,2)  -> 128 acc
// G1: d[16,32) = rr2[2,7) rr3[0,7) rr4[0,4)  -> 128 acc
// G2: d[32,49) = rr4[4,7) rr5[0,7) rr6[0,7)  -> 136 acc
template<int G>
__device__ __forceinline__ void accumulate(
    const float* __restrict__ s1, const float* __restrict__ s2,
    int tyl, int txl, float* __restrict__ acc)
{
#pragma unroll 1
    for (int c = 0; c < KC; ++c) {
        const float* frow = s1 + c * S1_CH + tyl * S1_ROW + txl * 8;
        float4 fa = ((const float4*)frow)[0];
        float4 fb = ((const float4*)frow)[1];
        float f[8] = { fa.x, fa.y, fa.z, fa.w, fb.x, fb.y, fb.z, fb.w };

        const float* rb = s2 + c * S2_CH + tyl * S2_ROW + txl * 8;
        if (G == 0) {
            row_acc<0, 7>(rb + 0 * S2_ROW, f, acc + 0);
            row_acc<0, 7>(rb + 1 * S2_ROW, f, acc + 56);
            row_acc<0, 2>(rb + 2 * S2_ROW, f, acc + 112);
        } else if (G == 1) {
            row_acc<2, 7>(rb + 2 * S2_ROW, f, acc + 0);
            row_acc<0, 7>(rb + 3 * S2_ROW, f, acc + 40);
            row_acc<0, 4>(rb + 4 * S2_ROW, f, acc + 96);
        } else {
            row_acc<4, 7>(rb + 4 * S2_ROW, f, acc + 0);
            row_acc<0, 7>(rb + 5 * S2_ROW, f, acc + 24);
            row_acc<0, 7>(rb + 6 * S2_ROW, f, acc + 80);
        }
    }
}

template<int NSEG>
__device__ __forceinline__ void store_seg(
    float* __restrict__ out, const float* __restrict__ acc,
    int b, int y, int x, int dbase)
{
    const float invC = 1.0f / (float)C_;
#pragma unroll
    for (int i = 0; i < NSEG; ++i) {
        float* op = out + (((size_t)b * ND + dbase + i) * H_ + y) * W_ + x;
        float4 o0, o1;
        o0.x = acc[i * 8 + 0] * invC;
        o0.y = acc[i * 8 + 1] * invC;
        o0.z = acc[i * 8 + 2] * invC;
        o0.w = acc[i * 8 + 3] * invC;
        o1.x = acc[i * 8 + 4] * invC;
        o1.y = acc[i * 8 + 5] * invC;
        o1.z = acc[i * 8 + 6] * invC;
        o1.w = acc[i * 8 + 7] * invC;
        ((float4*)op)[0] = o0;
        ((float4*)op)[1] = o1;
    }
}

__global__ void __launch_bounds__(NT, 2)
corr_kernel(const float* __restrict__ first,
            const float* __restrict__ second,
            float* __restrict__ out)
{
    extern __shared__ float smem[];
    const int tid = threadIdx.x;
    const int wg   = tid >> 6;        // group 0,1,2 (displacement split)
    const int wtid = tid & 63;
    const int bx = blockIdx.x, by = blockIdx.y, b = blockIdx.z;
    const int x0 = bx * TX, y0 = by * TY;
    const int txl = wtid & 3;         // 0..3, owns 8 x-pixels
    const int tyl = wtid >> 2;        // 0..15, one y-row

    const size_t HW = (size_t)H_ * W_;
    const float* fbase = first  + (size_t)b * C_ * HW;
    const float* sbase = second + (size_t)b * C_ * HW;

    float acc[136];
#pragma unroll
    for (int i = 0; i < 136; ++i) acc[i] = 0.0f;

    load_chunk(smem, smem + S1_SIZE, fbase, sbase, 0, x0, y0, tid);
    cp_commit();

#pragma unroll 1
    for (int k = 0; k < NCHUNK; ++k) {
        if (k < NCHUNK - 1) {
            float* nb = smem + ((k + 1) & 1) * BUF_SIZE;
            load_chunk(nb, nb + S1_SIZE, fbase, sbase, (k + 1) * KC, x0, y0, tid);
            cp_commit();
            asm volatile("cp.async.wait_group 1;\n" ::: "memory");
        } else {
            asm volatile("cp.async.wait_group 0;\n" ::: "memory");
        }
        __syncthreads();

        const float* s1 = smem + (k & 1) * BUF_SIZE;
        const float* s2 = s1 + S1_SIZE;

        if (wg == 0)      accumulate<0>(s1, s2, tyl, txl, acc);
        else if (wg == 1) accumulate<1>(s1, s2, tyl, txl, acc);
        else              accumulate<2>(s1, s2, tyl, txl, acc);

        __syncthreads();
    }

    const int y = y0 + tyl;
    const int x = x0 + txl * 8;
    if (wg == 0)      store_seg<16>(out, acc, b, y, x, 0);
    else if (wg == 1) store_seg<16>(out, acc, b, y, x, 16);
    else              store_seg<17>(out, acc, b, y, x, 32);
}

extern "C" void kernel_launch(void* const* d_in, const int* in_sizes, int n_in,
                              void* d_out, int out_size)
{
    const float* first  = (const float*)d_in[0];
    const float* second = (const float*)d_in[1];
    float* out = (float*)d_out;

    cudaFuncSetAttribute(corr_kernel,
                         cudaFuncAttributeMaxDynamicSharedMemorySize,
                         (int)SMEM_BYTES);

    dim3 grid(W_ / TX, H_ / TY, B_);   // 14 x 12 x 8 = 1344 CTAs
    dim3 block(NT);
    corr_kernel<<<grid, block, SMEM_BYTES>>>(first, second, out);
}